// round 12
// baseline (speedup 1.0000x reference)
#include <cuda_runtime.h>
#include <cuda_fp16.h>
#include <cstdint>

#define NMAX 50000
#define EMAX 1600000
#define DD 128

// ---- scratch (static device globals; no allocation allowed) ----
__device__ __half g_suph[(size_t)NMAX * DD];  // support in fp16 (SpMM gather operand)
__device__ __half g_hh[(size_t)NMAX * DD];    // hidden after layer 1 (fp16)
__device__ __half g_w1h[DD * DD];             // W1^T in fp16 ([n][k], K-major)
__device__ __half g_w2h[DD * DD];             // W2^T in fp16
__device__ int    g_rowptr[NMAX + 1];
__device__ int    g_deg[NMAX];
__device__ int    g_fill[NMAX];
__device__ int2   g_csr[EMAX];                // packed (src, weight-bits)
__device__ unsigned int g_state[64];          // lookback scan states

// ================= helpers =================

__device__ __forceinline__ uint32_t smem_u32(const void* p) {
    uint32_t a;
    asm("{ .reg .u64 t; cvta.to.shared.u64 t, %1; cvt.u32.u64 %0, t; }"
        : "=r"(a) : "l"(p));
    return a;
}

__device__ __forceinline__ void ldmatrix_x4(uint32_t& r0, uint32_t& r1,
                                            uint32_t& r2, uint32_t& r3, uint32_t addr) {
    asm volatile("ldmatrix.sync.aligned.m8n8.x4.shared.b16 {%0,%1,%2,%3}, [%4];"
                 : "=r"(r0), "=r"(r1), "=r"(r2), "=r"(r3) : "r"(addr));
}

__device__ __forceinline__ void mma16816(float* d, const uint32_t* a,
                                         const uint32_t* b, const float* c) {
    asm volatile(
        "mma.sync.aligned.m16n8k16.row.col.f32.f16.f16.f32 "
        "{%0,%1,%2,%3}, {%4,%5,%6,%7}, {%8,%9}, {%10,%11,%12,%13};"
        : "=f"(d[0]), "=f"(d[1]), "=f"(d[2]), "=f"(d[3])
        : "r"(a[0]), "r"(a[1]), "r"(a[2]), "r"(a[3]),
          "r"(b[0]), "r"(b[1]),
          "f"(c[0]), "f"(c[1]), "f"(c[2]), "f"(c[3]));
}

// ================= W convert/transpose (once per launch) =================

__global__ void k_wconv(const float* __restrict__ W1, const float* __restrict__ W2) {
    int i = blockIdx.x * blockDim.x + threadIdx.x;
    if (i < DD * DD) {
        int k = i >> 7, nn = i & 127;
        g_w1h[nn * DD + k] = __float2half(W1[i]);
        g_w2h[nn * DD + k] = __float2half(W2[i]);
    }
}

// ================= single-pass scan (decoupled lookback) =================
// 25 blocks only — all co-resident in wave 1, so predecessor spin is safe.

#define STILE 2048

__global__ void k_scan(int n, int e) {
    __shared__ int swarp[8];
    __shared__ int sprefix;
    int b = blockIdx.x, t = threadIdx.x, lane = t & 31, wid = t >> 5;
    int base = b * STILE + t * 8;

    int v[8];
    int s = 0;
#pragma unroll
    for (int i = 0; i < 8; i++) {
        int idx = base + i;
        v[i] = (idx < n) ? g_deg[idx] : 0;
        s += v[i];
    }
    int inc = s;
#pragma unroll
    for (int o = 1; o < 32; o <<= 1) {
        int y = __shfl_up_sync(0xffffffffu, inc, o);
        if (lane >= o) inc += y;
    }
    if (lane == 31) swarp[wid] = inc;
    __syncthreads();

    if (wid == 0) {
        int ws = (lane < 8) ? swarp[lane] : 0;
        int wi = ws;
#pragma unroll
        for (int o = 1; o < 8; o <<= 1) {
            int y = __shfl_up_sync(0xffffffffu, wi, o);
            if (lane >= o) wi += y;
        }
        int btotal = __shfl_sync(0xffffffffu, wi, 7);
        if (lane < 8) swarp[lane] = wi - ws;   // exclusive warp offsets
        if (lane == 0) {
            unsigned int agg = (unsigned int)btotal & 0x3FFFFFFFu;
            if (b == 0) {
                sprefix = 0;
                __threadfence();
                g_state[0] = agg | 0x80000000u;   // P
            } else {
                g_state[b] = agg | 0x40000000u;   // A
                __threadfence();
                unsigned int run = 0;
                int j = b - 1;
                while (true) {
                    unsigned int st = *(volatile unsigned int*)&g_state[j];
                    if (st & 0x80000000u) { run += st & 0x3FFFFFFFu; break; }
                    if (st & 0x40000000u) { run += st & 0x3FFFFFFFu; j--; }
                }
                sprefix = (int)run;
                __threadfence();
                g_state[b] = ((run + agg) & 0x3FFFFFFFu) | 0x80000000u;
            }
        }
    }
    __syncthreads();

    int run = sprefix + swarp[wid] + (inc - s);
#pragma unroll
    for (int i = 0; i < 8; i++) {
        int idx = base + i;
        if (idx < n) { g_rowptr[idx] = run; g_fill[idx] = run; }
        run += v[i];
    }
    if (b == 0 && t == 0) g_rowptr[n] = e;
}

// ================= fill (packed int2 CSR, 4 edges/thread) =================

__global__ void k_fill(const int* __restrict__ src, const int* __restrict__ dst,
                       const float* __restrict__ w, int e) {
    int base4 = (blockIdx.x * blockDim.x + threadIdx.x) * 4;
    if (base4 + 4 <= e) {
        int4 d4 = *reinterpret_cast<const int4*>(dst + base4);
        int4 s4 = *reinterpret_cast<const int4*>(src + base4);
        float4 w4 = *reinterpret_cast<const float4*>(w + base4);
        int p0 = atomicAdd(&g_fill[d4.x], 1);
        int p1 = atomicAdd(&g_fill[d4.y], 1);
        int p2 = atomicAdd(&g_fill[d4.z], 1);
        int p3 = atomicAdd(&g_fill[d4.w], 1);
        g_csr[p0] = make_int2(s4.x, __float_as_int(w4.x));
        g_csr[p1] = make_int2(s4.y, __float_as_int(w4.y));
        g_csr[p2] = make_int2(s4.z, __float_as_int(w4.z));
        g_csr[p3] = make_int2(s4.w, __float_as_int(w4.w));
    } else {
        for (int i = base4; i < e; i++) {
            int d = dst[i];
            int p = atomicAdd(&g_fill[d], 1);
            g_csr[p] = make_int2(src[i], __float_as_int(w[i]));
        }
    }
}

// ================= HMMA GEMM: C[n x 128](fp16) = X @ W (+fused hist) ============

#define AS_STRIDE 136
#define GEMM_SMEM (2 * 128 * AS_STRIDE * 2)   // 69632 B

__global__ __launch_bounds__(256)
void k_gemm_mma(const void* __restrict__ Xv, int x_is_half,
                const __half* __restrict__ Wt, __half* __restrict__ C, int n,
                const int* __restrict__ hist_dst, int e, int gemmBlocks) {
    if (blockIdx.x >= gemmBlocks) {
        if (hist_dst) {
            int stride = (gridDim.x - gemmBlocks) * blockDim.x;
            for (int i = (blockIdx.x - gemmBlocks) * blockDim.x + threadIdx.x;
                 i < e; i += stride)
                atomicAdd(&g_deg[hist_dst[i]], 1);
        }
        return;
    }

    extern __shared__ __half sm[];
    __half* As = sm;                       // [128][AS_STRIDE]
    __half* Bs = sm + 128 * AS_STRIDE;     // [128][AS_STRIDE]

    int t = threadIdx.x, wid = t >> 5, lane = t & 31;
    int wm = wid >> 1, wn = wid & 1;
    int rowBase = blockIdx.x * 128;

    for (int i = t; i < 4096; i += 256) {
        int r = i >> 5, c4 = i & 31;
        uint2 v = *reinterpret_cast<const uint2*>(Wt + r * 128 + c4 * 4);
        *reinterpret_cast<uint2*>(Bs + r * AS_STRIDE + c4 * 4) = v;
    }
    if (x_is_half) {
        const __half* X = (const __half*)Xv;
        for (int i = t; i < 4096; i += 256) {
            int r = i >> 5, c4 = i & 31;
            int gr = rowBase + r;
            uint2 v = make_uint2(0u, 0u);
            if (gr < n) v = *reinterpret_cast<const uint2*>(X + (size_t)gr * 128 + c4 * 4);
            *reinterpret_cast<uint2*>(As + r * AS_STRIDE + c4 * 4) = v;
        }
    } else {
        const float* X = (const float*)Xv;
        for (int i = t; i < 4096; i += 256) {
            int r = i >> 5, c4 = i & 31;
            int gr = rowBase + r;
            float4 v = make_float4(0.f, 0.f, 0.f, 0.f);
            if (gr < n) v = *reinterpret_cast<const float4*>(X + (size_t)gr * 128 + c4 * 4);
            __half2 h0 = __floats2half2_rn(v.x, v.y);
            __half2 h1 = __floats2half2_rn(v.z, v.w);
            uint2 p;
            p.x = *reinterpret_cast<unsigned int*>(&h0);
            p.y = *reinterpret_cast<unsigned int*>(&h1);
            *reinterpret_cast<uint2*>(As + r * AS_STRIDE + c4 * 4) = p;
        }
    }
    __syncthreads();

    float acc[2][8][4];
#pragma unroll
    for (int mi = 0; mi < 2; mi++)
#pragma unroll
        for (int ni = 0; ni < 8; ni++)
#pragma unroll
            for (int j = 0; j < 4; j++) acc[mi][ni][j] = 0.0f;

    uint32_t asBase = smem_u32(As);
    uint32_t bsBase = smem_u32(Bs);

    int a_row_off = (lane & 15);
    int a_k_off = (lane >> 4) * 8;
    int b_n_off = (lane & 7) + ((lane >> 4) & 1) * 8;
    int b_k_off = ((lane >> 3) & 1) * 8;

#pragma unroll
    for (int kk = 0; kk < 8; kk++) {
        int kc = kk * 16;
        uint32_t af[2][4];
#pragma unroll
        for (int mi = 0; mi < 2; mi++) {
            int row = wm * 32 + mi * 16 + a_row_off;
            uint32_t addr = asBase + (uint32_t)(row * AS_STRIDE + kc + a_k_off) * 2u;
            ldmatrix_x4(af[mi][0], af[mi][1], af[mi][2], af[mi][3], addr);
        }
        uint32_t bf[4][4];
#pragma unroll
        for (int bg = 0; bg < 4; bg++) {
            int nrow = wn * 64 + bg * 16 + b_n_off;
            uint32_t addr = bsBase + (uint32_t)(nrow * AS_STRIDE + kc + b_k_off) * 2u;
            ldmatrix_x4(bf[bg][0], bf[bg][1], bf[bg][2], bf[bg][3], addr);
        }
#pragma unroll
        for (int mi = 0; mi < 2; mi++)
#pragma unroll
            for (int ni = 0; ni < 8; ni++) {
                const uint32_t* bp = &bf[ni >> 1][(ni & 1) * 2];
                mma16816(acc[mi][ni], af[mi], bp, acc[mi][ni]);
            }
    }

    int g = lane >> 2, tq = lane & 3;
#pragma unroll
    for (int mi = 0; mi < 2; mi++) {
        int r0 = rowBase + wm * 32 + mi * 16 + g;
#pragma unroll
        for (int ni = 0; ni < 8; ni++) {
            int col = wn * 64 + ni * 8 + tq * 2;
            __half2 lo = __floats2half2_rn(acc[mi][ni][0], acc[mi][ni][1]);
            __half2 hi = __floats2half2_rn(acc[mi][ni][2], acc[mi][ni][3]);
            if (r0 < n)
                *reinterpret_cast<unsigned int*>(C + (size_t)r0 * 128 + col) =
                    *reinterpret_cast<unsigned int*>(&lo);
            if (r0 + 8 < n)
                *reinterpret_cast<unsigned int*>(C + (size_t)(r0 + 8) * 128 + col) =
                    *reinterpret_cast<unsigned int*>(&hi);
        }
    }
}

// ================= SpMM (CSR by dst, warp per row, fp16 gather, fp32 acc) =======

__global__ void k_spmm(const __half* __restrict__ sup, const float* __restrict__ bias,
                       float* __restrict__ outf, __half* __restrict__ outh,
                       int n, int do_relu) {
    int gt = blockIdx.x * blockDim.x + threadIdx.x;
    int row = gt >> 5;
    int lane = gt & 31;
    if (row >= n) return;

    float4 acc = *reinterpret_cast<const float4*>(bias + lane * 4);
    int e0 = g_rowptr[row];
    int e1 = g_rowptr[row + 1];

    int e = e0;
    for (; e + 4 <= e1; e += 4) {
        int2 c0 = g_csr[e];
        int2 c1 = g_csr[e + 1];
        int2 c2 = g_csr[e + 2];
        int2 c3 = g_csr[e + 3];
        float w0 = __int_as_float(c0.y);
        float w1 = __int_as_float(c1.y);
        float w2 = __int_as_float(c2.y);
        float w3 = __int_as_float(c3.y);
        uint2 p0 = *reinterpret_cast<const uint2*>(sup + (size_t)c0.x * 128 + lane * 4);
        uint2 p1 = *reinterpret_cast<const uint2*>(sup + (size_t)c1.x * 128 + lane * 4);
        uint2 p2 = *reinterpret_cast<const uint2*>(sup + (size_t)c2.x * 128 + lane * 4);
        uint2 p3 = *reinterpret_cast<const uint2*>(sup + (size_t)c3.x * 128 + lane * 4);
        float2 a0 = __half22float2(*reinterpret_cast<__half2*>(&p0.x));
        float2 b0 = __half22float2(*reinterpret_cast<__half2*>(&p0.y));
        float2 a1 = __half22float2(*reinterpret_cast<__half2*>(&p1.x));
        float2 b1 = __half22float2(*reinterpret_cast<__half2*>(&p1.y));
        float2 a2 = __half22float2(*reinterpret_cast<__half2*>(&p2.x));
        float2 b2 = __half22float2(*reinterpret_cast<__half2*>(&p2.y));
        float2 a3 = __half22float2(*reinterpret_cast<__half2*>(&p3.x));
        float2 b3 = __half22float2(*reinterpret_cast<__half2*>(&p3.y));
        acc.x = fmaf(w0, a0.x, acc.x); acc.y = fmaf(w0, a0.y, acc.y);
        acc.z = fmaf(w0, b0.x, acc.z); acc.w = fmaf(w0, b0.y, acc.w);
        acc.x = fmaf(w1, a1.x, acc.x); acc.y = fmaf(w1, a1.y, acc.y);
        acc.z = fmaf(w1, b1.x, acc.z); acc.w = fmaf(w1, b1.y, acc.w);
        acc.x = fmaf(w2, a2.x, acc.x); acc.y = fmaf(w2, a2.y, acc.y);
        acc.z = fmaf(w2, b2.x, acc.z); acc.w = fmaf(w2, b2.y, acc.w);
        acc.x = fmaf(w3, a3.x, acc.x); acc.y = fmaf(w3, a3.y, acc.y);
        acc.z = fmaf(w3, b3.x, acc.z); acc.w = fmaf(w3, b3.y, acc.w);
    }
    for (; e < e1; e++) {
        int2 c = g_csr[e];
        float w = __int_as_float(c.y);
        uint2 p = *reinterpret_cast<const uint2*>(sup + (size_t)c.x * 128 + lane * 4);
        float2 a = __half22float2(*reinterpret_cast<__half2*>(&p.x));
        float2 b = __half22float2(*reinterpret_cast<__half2*>(&p.y));
        acc.x = fmaf(w, a.x, acc.x); acc.y = fmaf(w, a.y, acc.y);
        acc.z = fmaf(w, b.x, acc.z); acc.w = fmaf(w, b.y, acc.w);
    }

    if (do_relu) {
        acc.x = fmaxf(acc.x, 0.f);
        acc.y = fmaxf(acc.y, 0.f);
        acc.z = fmaxf(acc.z, 0.f);
        acc.w = fmaxf(acc.w, 0.f);
    }
    if (outf) {
        *reinterpret_cast<float4*>(outf + (size_t)row * 128 + lane * 4) = acc;
    } else {
        __half2 h0 = __floats2half2_rn(acc.x, acc.y);
        __half2 h1 = __floats2half2_rn(acc.z, acc.w);
        uint2 p;
        p.x = *reinterpret_cast<unsigned int*>(&h0);
        p.y = *reinterpret_cast<unsigned int*>(&h1);
        *reinterpret_cast<uint2*>(outh + (size_t)row * 128 + lane * 4) = p;
    }
}

// ================= launch =================

extern "C" void kernel_launch(void* const* d_in, const int* in_sizes, int n_in,
                              void* d_out, int out_size) {
    const float* features = (const float*)d_in[0];
    const int*   edge_src = (const int*)d_in[1];
    const int*   edge_dst = (const int*)d_in[2];
    const float* edge_w   = (const float*)d_in[3];
    const float* W1       = (const float*)d_in[4];
    const float* b1       = (const float*)d_in[5];
    const float* W2       = (const float*)d_in[6];
    const float* b2       = (const float*)d_in[7];
    float* out = (float*)d_out;

    int n = in_sizes[0] / DD;   // 50000
    int e = in_sizes[1];        // 1600000

    // device-global addresses
    __half *suph, *hh, *w1h, *w2h;
    int* degp;
    unsigned int* statep;
    cudaGetSymbolAddress((void**)&suph, g_suph);
    cudaGetSymbolAddress((void**)&hh, g_hh);
    cudaGetSymbolAddress((void**)&w1h, g_w1h);
    cudaGetSymbolAddress((void**)&w2h, g_w2h);
    cudaGetSymbolAddress((void**)&degp, g_deg);
    cudaGetSymbolAddress((void**)&statep, g_state);

    cudaFuncSetAttribute(k_gemm_mma, cudaFuncAttributeMaxDynamicSharedMemorySize, GEMM_SMEM);

    int gemm_blocks = (n + 127) / 128;              // 391
    int hist_blocks = 148;
    int spmm_blocks = (n * 32 + 255) / 256;
    int scan_blocks = (n + STILE - 1) / STILE;      // 25 (single wave — lookback safe)
    int fill_blocks = (e + 4 * 256 - 1) / (4 * 256);

    // ---- init + W convert ----
    cudaMemsetAsync(degp, 0, (size_t)n * sizeof(int), 0);
    cudaMemsetAsync(statep, 0, 64 * sizeof(unsigned int), 0);
    k_wconv<<<64, 256>>>(W1, W2);

    // ---- GEMM1 (HMMA) with fused edge-dst histogram ----
    k_gemm_mma<<<gemm_blocks + hist_blocks, 256, GEMM_SMEM>>>(
        features, 0, w1h, suph, n, edge_dst, e, gemm_blocks);

    // ---- CSR: scan, then fill (stream-ordered; no device-side join) ----
    k_scan<<<scan_blocks, 256>>>(n, e);
    k_fill<<<fill_blocks, 256>>>(edge_src, edge_dst, edge_w, e);

    // ---- layer 1 aggregate (fp16 out + relu) ----
    k_spmm<<<spmm_blocks, 256>>>(suph, b1, (float*)0, hh, n, 1);

    // ---- layer 2 ----
    k_gemm_mma<<<gemm_blocks, 256, GEMM_SMEM>>>(
        hh, 1, w2h, suph, n, (const int*)0, 0, gemm_blocks);
    k_spmm<<<spmm_blocks, 256>>>(suph, b2, out, (__half*)0, n, 0);
}

// round 14
// speedup vs baseline: 1.0099x; 1.0099x over previous
#include <cuda_runtime.h>
#include <cuda_fp16.h>
#include <cstdint>

#define NMAX 50000
#define EMAX 1600000
#define DD 128

// ---- scratch (static device globals; no allocation allowed) ----
__device__ __half g_suph[(size_t)NMAX * DD];  // support in fp16 (SpMM gather operand)
__device__ __half g_hh[(size_t)NMAX * DD];    // hidden after layer 1 (fp16)
__device__ __half g_w1h[DD * DD];             // W1^T in fp16 ([n][k], K-major)
__device__ __half g_w2h[DD * DD];             // W2^T in fp16
__device__ int    g_rowptr[NMAX + 1];
__device__ int    g_deg[NMAX];
__device__ int    g_fill[NMAX];
__device__ int2   g_csr[EMAX];                // packed (src, weight-bits)
__device__ unsigned int g_state[64];          // lookback scan states

// ================= helpers =================

__device__ __forceinline__ uint32_t smem_u32(const void* p) {
    uint32_t a;
    asm("{ .reg .u64 t; cvta.to.shared.u64 t, %1; cvt.u32.u64 %0, t; }"
        : "=r"(a) : "l"(p));
    return a;
}

__device__ __forceinline__ void ldmatrix_x4(uint32_t& r0, uint32_t& r1,
                                            uint32_t& r2, uint32_t& r3, uint32_t addr) {
    asm volatile("ldmatrix.sync.aligned.m8n8.x4.shared.b16 {%0,%1,%2,%3}, [%4];"
                 : "=r"(r0), "=r"(r1), "=r"(r2), "=r"(r3) : "r"(addr));
}

__device__ __forceinline__ void mma16816(float* d, const uint32_t* a,
                                         const uint32_t* b, const float* c) {
    asm volatile(
        "mma.sync.aligned.m16n8k16.row.col.f32.f16.f16.f32 "
        "{%0,%1,%2,%3}, {%4,%5,%6,%7}, {%8,%9}, {%10,%11,%12,%13};"
        : "=f"(d[0]), "=f"(d[1]), "=f"(d[2]), "=f"(d[3])
        : "r"(a[0]), "r"(a[1]), "r"(a[2]), "r"(a[3]),
          "r"(b[0]), "r"(b[1]),
          "f"(c[0]), "f"(c[1]), "f"(c[2]), "f"(c[3]));
}

// ================= W convert/transpose =================

__global__ void k_wconv(const float* __restrict__ W1, const float* __restrict__ W2) {
    int i = blockIdx.x * blockDim.x + threadIdx.x;
    if (i < DD * DD) {
        int k = i >> 7, nn = i & 127;
        g_w1h[nn * DD + k] = __float2half(W1[i]);
        g_w2h[nn * DD + k] = __float2half(W2[i]);
    }
}

// ================= histogram =================

__global__ void k_hist(const int* __restrict__ dst, int e) {
    int i = blockIdx.x * blockDim.x + threadIdx.x;
    if (i < e) atomicAdd(&g_deg[dst[i]], 1);
}

// ================= single-pass scan (decoupled lookback) =================
// 25 blocks only — all co-resident in wave 1, so predecessor spin is safe.

#define STILE 2048

__global__ void k_scan(int n, int e) {
    __shared__ int swarp[8];
    __shared__ int sprefix;
    int b = blockIdx.x, t = threadIdx.x, lane = t & 31, wid = t >> 5;
    int base = b * STILE + t * 8;

    int v[8];
    int s = 0;
#pragma unroll
    for (int i = 0; i < 8; i++) {
        int idx = base + i;
        v[i] = (idx < n) ? g_deg[idx] : 0;
        s += v[i];
    }
    int inc = s;
#pragma unroll
    for (int o = 1; o < 32; o <<= 1) {
        int y = __shfl_up_sync(0xffffffffu, inc, o);
        if (lane >= o) inc += y;
    }
    if (lane == 31) swarp[wid] = inc;
    __syncthreads();

    if (wid == 0) {
        int ws = (lane < 8) ? swarp[lane] : 0;
        int wi = ws;
#pragma unroll
        for (int o = 1; o < 8; o <<= 1) {
            int y = __shfl_up_sync(0xffffffffu, wi, o);
            if (lane >= o) wi += y;
        }
        int btotal = __shfl_sync(0xffffffffu, wi, 7);
        if (lane < 8) swarp[lane] = wi - ws;   // exclusive warp offsets
        if (lane == 0) {
            unsigned int agg = (unsigned int)btotal & 0x3FFFFFFFu;
            if (b == 0) {
                sprefix = 0;
                __threadfence();
                g_state[0] = agg | 0x80000000u;   // P
            } else {
                g_state[b] = agg | 0x40000000u;   // A
                __threadfence();
                unsigned int run = 0;
                int j = b - 1;
                while (true) {
                    unsigned int st = *(volatile unsigned int*)&g_state[j];
                    if (st & 0x80000000u) { run += st & 0x3FFFFFFFu; break; }
                    if (st & 0x40000000u) { run += st & 0x3FFFFFFFu; j--; }
                }
                sprefix = (int)run;
                __threadfence();
                g_state[b] = ((run + agg) & 0x3FFFFFFFu) | 0x80000000u;
            }
        }
    }
    __syncthreads();

    int run = sprefix + swarp[wid] + (inc - s);
#pragma unroll
    for (int i = 0; i < 8; i++) {
        int idx = base + i;
        if (idx < n) { g_rowptr[idx] = run; g_fill[idx] = run; }
        run += v[i];
    }
    if (b == 0 && t == 0) g_rowptr[n] = e;
}

// ================= fill (packed int2 CSR, 8 edges/thread) =================

__global__ void k_fill(const int* __restrict__ src, const int* __restrict__ dst,
                       const float* __restrict__ w, int e) {
    int base8 = (blockIdx.x * blockDim.x + threadIdx.x) * 8;
    if (base8 + 8 <= e) {
        int4 da = *reinterpret_cast<const int4*>(dst + base8);
        int4 db = *reinterpret_cast<const int4*>(dst + base8 + 4);
        int4 sa = *reinterpret_cast<const int4*>(src + base8);
        int4 sb = *reinterpret_cast<const int4*>(src + base8 + 4);
        float4 wa = *reinterpret_cast<const float4*>(w + base8);
        float4 wb = *reinterpret_cast<const float4*>(w + base8 + 4);
        int p0 = atomicAdd(&g_fill[da.x], 1);
        int p1 = atomicAdd(&g_fill[da.y], 1);
        int p2 = atomicAdd(&g_fill[da.z], 1);
        int p3 = atomicAdd(&g_fill[da.w], 1);
        int p4 = atomicAdd(&g_fill[db.x], 1);
        int p5 = atomicAdd(&g_fill[db.y], 1);
        int p6 = atomicAdd(&g_fill[db.z], 1);
        int p7 = atomicAdd(&g_fill[db.w], 1);
        g_csr[p0] = make_int2(sa.x, __float_as_int(wa.x));
        g_csr[p1] = make_int2(sa.y, __float_as_int(wa.y));
        g_csr[p2] = make_int2(sa.z, __float_as_int(wa.z));
        g_csr[p3] = make_int2(sa.w, __float_as_int(wa.w));
        g_csr[p4] = make_int2(sb.x, __float_as_int(wb.x));
        g_csr[p5] = make_int2(sb.y, __float_as_int(wb.y));
        g_csr[p6] = make_int2(sb.z, __float_as_int(wb.z));
        g_csr[p7] = make_int2(sb.w, __float_as_int(wb.w));
    } else {
        for (int i = base8; i < e; i++) {
            int d = dst[i];
            int p = atomicAdd(&g_fill[d], 1);
            g_csr[p] = make_int2(src[i], __float_as_int(w[i]));
        }
    }
}

// ================= HMMA GEMM: C[n x 128](fp16) = X @ W ============

#define AS_STRIDE 136
#define GEMM_SMEM (2 * 128 * AS_STRIDE * 2)   // 69632 B

__global__ __launch_bounds__(256)
void k_gemm_mma(const void* __restrict__ Xv, int x_is_half,
                const __half* __restrict__ Wt, __half* __restrict__ C, int n) {
    extern __shared__ __half sm[];
    __half* As = sm;                       // [128][AS_STRIDE]
    __half* Bs = sm + 128 * AS_STRIDE;     // [128][AS_STRIDE]

    int t = threadIdx.x, wid = t >> 5, lane = t & 31;
    int wm = wid >> 1, wn = wid & 1;
    int rowBase = blockIdx.x * 128;

    for (int i = t; i < 4096; i += 256) {
        int r = i >> 5, c4 = i & 31;
        uint2 v = *reinterpret_cast<const uint2*>(Wt + r * 128 + c4 * 4);
        *reinterpret_cast<uint2*>(Bs + r * AS_STRIDE + c4 * 4) = v;
    }
    if (x_is_half) {
        const __half* X = (const __half*)Xv;
        for (int i = t; i < 4096; i += 256) {
            int r = i >> 5, c4 = i & 31;
            int gr = rowBase + r;
            uint2 v = make_uint2(0u, 0u);
            if (gr < n) v = *reinterpret_cast<const uint2*>(X + (size_t)gr * 128 + c4 * 4);
            *reinterpret_cast<uint2*>(As + r * AS_STRIDE + c4 * 4) = v;
        }
    } else {
        const float* X = (const float*)Xv;
        for (int i = t; i < 4096; i += 256) {
            int r = i >> 5, c4 = i & 31;
            int gr = rowBase + r;
            float4 v = make_float4(0.f, 0.f, 0.f, 0.f);
            if (gr < n) v = *reinterpret_cast<const float4*>(X + (size_t)gr * 128 + c4 * 4);
            __half2 h0 = __floats2half2_rn(v.x, v.y);
            __half2 h1 = __floats2half2_rn(v.z, v.w);
            uint2 p;
            p.x = *reinterpret_cast<unsigned int*>(&h0);
            p.y = *reinterpret_cast<unsigned int*>(&h1);
            *reinterpret_cast<uint2*>(As + r * AS_STRIDE + c4 * 4) = p;
        }
    }
    __syncthreads();

    float acc[2][8][4];
#pragma unroll
    for (int mi = 0; mi < 2; mi++)
#pragma unroll
        for (int ni = 0; ni < 8; ni++)
#pragma unroll
            for (int j = 0; j < 4; j++) acc[mi][ni][j] = 0.0f;

    uint32_t asBase = smem_u32(As);
    uint32_t bsBase = smem_u32(Bs);

    int a_row_off = (lane & 15);
    int a_k_off = (lane >> 4) * 8;
    int b_n_off = (lane & 7) + ((lane >> 4) & 1) * 8;
    int b_k_off = ((lane >> 3) & 1) * 8;

#pragma unroll
    for (int kk = 0; kk < 8; kk++) {
        int kc = kk * 16;
        uint32_t af[2][4];
#pragma unroll
        for (int mi = 0; mi < 2; mi++) {
            int row = wm * 32 + mi * 16 + a_row_off;
            uint32_t addr = asBase + (uint32_t)(row * AS_STRIDE + kc + a_k_off) * 2u;
            ldmatrix_x4(af[mi][0], af[mi][1], af[mi][2], af[mi][3], addr);
        }
        uint32_t bf[4][4];
#pragma unroll
        for (int bg = 0; bg < 4; bg++) {
            int nrow = wn * 64 + bg * 16 + b_n_off;
            uint32_t addr = bsBase + (uint32_t)(nrow * AS_STRIDE + kc + b_k_off) * 2u;
            ldmatrix_x4(bf[bg][0], bf[bg][1], bf[bg][2], bf[bg][3], addr);
        }
#pragma unroll
        for (int mi = 0; mi < 2; mi++)
#pragma unroll
            for (int ni = 0; ni < 8; ni++) {
                const uint32_t* bp = &bf[ni >> 1][(ni & 1) * 2];
                mma16816(acc[mi][ni], af[mi], bp, acc[mi][ni]);
            }
    }

    int g = lane >> 2, tq = lane & 3;
#pragma unroll
    for (int mi = 0; mi < 2; mi++) {
        int r0 = rowBase + wm * 32 + mi * 16 + g;
#pragma unroll
        for (int ni = 0; ni < 8; ni++) {
            int col = wn * 64 + ni * 8 + tq * 2;
            __half2 lo = __floats2half2_rn(acc[mi][ni][0], acc[mi][ni][1]);
            __half2 hi = __floats2half2_rn(acc[mi][ni][2], acc[mi][ni][3]);
            if (r0 < n)
                *reinterpret_cast<unsigned int*>(C + (size_t)r0 * 128 + col) =
                    *reinterpret_cast<unsigned int*>(&lo);
            if (r0 + 8 < n)
                *reinterpret_cast<unsigned int*>(C + (size_t)(r0 + 8) * 128 + col) =
                    *reinterpret_cast<unsigned int*>(&hi);
        }
    }
}

// ================= SpMM (CSR by dst, warp per row, fp16 gather, fp32 acc) =======

__global__ void k_spmm(const __half* __restrict__ sup, const float* __restrict__ bias,
                       float* __restrict__ outf, __half* __restrict__ outh,
                       int n, int do_relu) {
    int gt = blockIdx.x * blockDim.x + threadIdx.x;
    int row = gt >> 5;
    int lane = gt & 31;
    if (row >= n) return;

    float4 acc = *reinterpret_cast<const float4*>(bias + lane * 4);
    int e0 = g_rowptr[row];
    int e1 = g_rowptr[row + 1];

    int e = e0;
    for (; e + 4 <= e1; e += 4) {
        int2 c0 = g_csr[e];
        int2 c1 = g_csr[e + 1];
        int2 c2 = g_csr[e + 2];
        int2 c3 = g_csr[e + 3];
        float w0 = __int_as_float(c0.y);
        float w1 = __int_as_float(c1.y);
        float w2 = __int_as_float(c2.y);
        float w3 = __int_as_float(c3.y);
        uint2 p0 = *reinterpret_cast<const uint2*>(sup + (size_t)c0.x * 128 + lane * 4);
        uint2 p1 = *reinterpret_cast<const uint2*>(sup + (size_t)c1.x * 128 + lane * 4);
        uint2 p2 = *reinterpret_cast<const uint2*>(sup + (size_t)c2.x * 128 + lane * 4);
        uint2 p3 = *reinterpret_cast<const uint2*>(sup + (size_t)c3.x * 128 + lane * 4);
        float2 a0 = __half22float2(*reinterpret_cast<__half2*>(&p0.x));
        float2 b0 = __half22float2(*reinterpret_cast<__half2*>(&p0.y));
        float2 a1 = __half22float2(*reinterpret_cast<__half2*>(&p1.x));
        float2 b1 = __half22float2(*reinterpret_cast<__half2*>(&p1.y));
        float2 a2 = __half22float2(*reinterpret_cast<__half2*>(&p2.x));
        float2 b2 = __half22float2(*reinterpret_cast<__half2*>(&p2.y));
        float2 a3 = __half22float2(*reinterpret_cast<__half2*>(&p3.x));
        float2 b3 = __half22float2(*reinterpret_cast<__half2*>(&p3.y));
        acc.x = fmaf(w0, a0.x, acc.x); acc.y = fmaf(w0, a0.y, acc.y);
        acc.z = fmaf(w0, b0.x, acc.z); acc.w = fmaf(w0, b0.y, acc.w);
        acc.x = fmaf(w1, a1.x, acc.x); acc.y = fmaf(w1, a1.y, acc.y);
        acc.z = fmaf(w1, b1.x, acc.z); acc.w = fmaf(w1, b1.y, acc.w);
        acc.x = fmaf(w2, a2.x, acc.x); acc.y = fmaf(w2, a2.y, acc.y);
        acc.z = fmaf(w2, b2.x, acc.z); acc.w = fmaf(w2, b2.y, acc.w);
        acc.x = fmaf(w3, a3.x, acc.x); acc.y = fmaf(w3, a3.y, acc.y);
        acc.z = fmaf(w3, b3.x, acc.z); acc.w = fmaf(w3, b3.y, acc.w);
    }
    for (; e < e1; e++) {
        int2 c = g_csr[e];
        float w = __int_as_float(c.y);
        uint2 p = *reinterpret_cast<const uint2*>(sup + (size_t)c.x * 128 + lane * 4);
        float2 a = __half22float2(*reinterpret_cast<__half2*>(&p.x));
        float2 b = __half22float2(*reinterpret_cast<__half2*>(&p.y));
        acc.x = fmaf(w, a.x, acc.x); acc.y = fmaf(w, a.y, acc.y);
        acc.z = fmaf(w, b.x, acc.z); acc.w = fmaf(w, b.y, acc.w);
    }

    if (do_relu) {
        acc.x = fmaxf(acc.x, 0.f);
        acc.y = fmaxf(acc.y, 0.f);
        acc.z = fmaxf(acc.z, 0.f);
        acc.w = fmaxf(acc.w, 0.f);
    }
    if (outf) {
        *reinterpret_cast<float4*>(outf + (size_t)row * 128 + lane * 4) = acc;
    } else {
        __half2 h0 = __floats2half2_rn(acc.x, acc.y);
        __half2 h1 = __floats2half2_rn(acc.z, acc.w);
        uint2 p;
        p.x = *reinterpret_cast<unsigned int*>(&h0);
        p.y = *reinterpret_cast<unsigned int*>(&h1);
        *reinterpret_cast<uint2*>(outh + (size_t)row * 128 + lane * 4) = p;
    }
}

// ================= launch =================

extern "C" void kernel_launch(void* const* d_in, const int* in_sizes, int n_in,
                              void* d_out, int out_size) {
    const float* features = (const float*)d_in[0];
    const int*   edge_src = (const int*)d_in[1];
    const int*   edge_dst = (const int*)d_in[2];
    const float* edge_w   = (const float*)d_in[3];
    const float* W1       = (const float*)d_in[4];
    const float* b1       = (const float*)d_in[5];
    const float* W2       = (const float*)d_in[6];
    const float* b2       = (const float*)d_in[7];
    float* out = (float*)d_out;

    int n = in_sizes[0] / DD;   // 50000
    int e = in_sizes[1];        // 1600000

    // lazy host-side stream/event objects (created once, outside capture;
    // host objects only — no device memory)
    static cudaStream_t sB = 0;
    static cudaEvent_t evFork = 0, evJoin = 0;
    if (!sB) {
        cudaStreamCreateWithFlags(&sB, cudaStreamNonBlocking);
        cudaEventCreateWithFlags(&evFork, cudaEventDisableTiming);
        cudaEventCreateWithFlags(&evJoin, cudaEventDisableTiming);
    }

    // device-global addresses
    __half *suph, *hh, *w1h, *w2h;
    int* degp;
    unsigned int* statep;
    cudaGetSymbolAddress((void**)&suph, g_suph);
    cudaGetSymbolAddress((void**)&hh, g_hh);
    cudaGetSymbolAddress((void**)&w1h, g_w1h);
    cudaGetSymbolAddress((void**)&w2h, g_w2h);
    cudaGetSymbolAddress((void**)&degp, g_deg);
    cudaGetSymbolAddress((void**)&statep, g_state);

    cudaFuncSetAttribute(k_gemm_mma, cudaFuncAttributeMaxDynamicSharedMemorySize, GEMM_SMEM);

    int gemm_blocks = (n + 127) / 128;              // 391
    int spmm_blocks = (n * 32 + 255) / 256;
    int scan_blocks = (n + STILE - 1) / STILE;      // 25 (single wave — lookback safe)
    int fill_blocks = (e + 8 * 256 - 1) / (8 * 256);
    int hist_blocks = (e + 511) / 512;

    // ---- stream 0: init memsets (deg must be zero before hist) ----
    cudaMemsetAsync(degp, 0, (size_t)n * sizeof(int), 0);
    cudaMemsetAsync(statep, 0, 64 * sizeof(unsigned int), 0);

    // ---- fork: CSR chain on sB, GEMM path on stream 0 ----
    cudaEventRecord(evFork, 0);
    cudaStreamWaitEvent(sB, evFork, 0);

    // branch B: hist -> scan -> fill
    k_hist<<<hist_blocks, 512, 0, sB>>>(edge_dst, e);
    k_scan<<<scan_blocks, 256, 0, sB>>>(n, e);
    k_fill<<<fill_blocks, 256, 0, sB>>>(edge_src, edge_dst, edge_w, e);
    cudaEventRecord(evJoin, sB);

    // branch A: wconv -> gemm1
    k_wconv<<<64, 256>>>(W1, W2);
    k_gemm_mma<<<gemm_blocks, 256, GEMM_SMEM>>>(features, 0, w1h, suph, n);

    // ---- join ----
    cudaStreamWaitEvent(0, evJoin, 0);

    // ---- layer 1 aggregate (fp16 out + relu) ----
    k_spmm<<<spmm_blocks, 256>>>(suph, b1, (float*)0, hh, n, 1);

    // ---- layer 2 ----
    k_gemm_mma<<<gemm_blocks, 256, GEMM_SMEM>>>(hh, 1, w2h, suph, n);
    k_spmm<<<spmm_blocks, 256>>>(suph, b2, out, (__half*)0, n, 0);
}